// round 9
// baseline (speedup 1.0000x reference)
#include <cuda_runtime.h>
#include <math.h>

#define NA 8192
#define NV 4096
#define NN 12288      // NA + NV
#define FDIM 64
#define ADIM 128
#define QKVS 384
#define KAA 10
#define KVV 15
#define MAXDEG 30
#define LTOT 8
#define OUTD 128

// ---------------- device scratch (no allocations allowed) ----------------
__device__ float  g_h[NN * ADIM];
__device__ float  g_qkv[NN * QKVS];
__device__ float  g_wqkv[LTOT * ADIM * QKVS];
__device__ float4 g_apos4[NA];
__device__ float4 g_vpos4[NV];
__device__ int    g_aa[NA * KAA];
__device__ int    g_av[NV * KVV];
__device__ int    g_vv[NV * KVV];
__device__ int    g_Uidx[NN * MAXDEG];
__device__ float  g_Uew[NN * MAXDEG];
__device__ float  g_paas[NA * 8];
__device__ float  g_paad[NA * 8];
__device__ float  g_pavd[NV * 8];
__device__ float  g_pavs[NA * 8];
__device__ float  g_pvvs[NV * 8];
__device__ float  g_pvvd[NV * 8];
__device__ float  g_feat[NV * 640];
__device__ float  g_hidden[NV * ADIM];

// ---------------- generic tiled GEMM: C[M,N] = A[M,K] @ B[K,N] (+bias)(+relu)
// grid = (M/64, N/64), block = 256 threads, each thread 4x4 outputs
__global__ void gemm64(const float* __restrict__ A, const float* __restrict__ B,
                       const float* __restrict__ bias, float* __restrict__ C,
                       int K, int N, int doRelu, int ldc)
{
    __shared__ __align__(16) float As[16][64];
    __shared__ __align__(16) float Bs[16][64];
    int tid = threadIdx.x;
    int tx = tid & 15, ty = tid >> 4;
    int bm = blockIdx.x << 6, bn = blockIdx.y << 6;
    int arow = tid >> 2, acol = (tid & 3) << 2;
    int brow = tid >> 4, bcol = (tid & 15) << 2;
    const float* Ap = A + (size_t)(bm + arow) * K + acol;
    const float* Bp = B + (size_t)brow * N + bn + bcol;

    float acc00=0,acc01=0,acc02=0,acc03=0;
    float acc10=0,acc11=0,acc12=0,acc13=0;
    float acc20=0,acc21=0,acc22=0,acc23=0;
    float acc30=0,acc31=0,acc32=0,acc33=0;

    for (int k0 = 0; k0 < K; k0 += 16) {
        float4 avv = *(const float4*)(Ap + k0);
        float4 bvv = *(const float4*)(Bp + (size_t)k0 * N);
        As[acol + 0][arow] = avv.x;
        As[acol + 1][arow] = avv.y;
        As[acol + 2][arow] = avv.z;
        As[acol + 3][arow] = avv.w;
        *(float4*)(&Bs[brow][bcol]) = bvv;
        __syncthreads();
#pragma unroll
        for (int kk = 0; kk < 16; ++kk) {
            float4 a = *(const float4*)(&As[kk][ty << 2]);
            float4 b = *(const float4*)(&Bs[kk][tx << 2]);
            acc00 = fmaf(a.x, b.x, acc00); acc01 = fmaf(a.x, b.y, acc01);
            acc02 = fmaf(a.x, b.z, acc02); acc03 = fmaf(a.x, b.w, acc03);
            acc10 = fmaf(a.y, b.x, acc10); acc11 = fmaf(a.y, b.y, acc11);
            acc12 = fmaf(a.y, b.z, acc12); acc13 = fmaf(a.y, b.w, acc13);
            acc20 = fmaf(a.z, b.x, acc20); acc21 = fmaf(a.z, b.y, acc21);
            acc22 = fmaf(a.z, b.z, acc22); acc23 = fmaf(a.z, b.w, acc23);
            acc30 = fmaf(a.w, b.x, acc30); acc31 = fmaf(a.w, b.y, acc31);
            acc32 = fmaf(a.w, b.z, acc32); acc33 = fmaf(a.w, b.w, acc33);
        }
        __syncthreads();
    }

    float accs[4][4] = {{acc00,acc01,acc02,acc03},{acc10,acc11,acc12,acc13},
                        {acc20,acc21,acc22,acc23},{acc30,acc31,acc32,acc33}};
#pragma unroll
    for (int i = 0; i < 4; ++i) {
        int r = bm + (ty << 2) + i;
#pragma unroll
        for (int j = 0; j < 4; ++j) {
            int c = bn + (tx << 2) + j;
            float vv = accs[i][j];
            if (bias) vv += bias[c];
            if (doRelu) vv = fmaxf(vv, 0.f);
            C[(size_t)r * ldc + c] = vv;
        }
    }
}

// ---------------- position packing: (x, y, z, |p|^2) ----------------
__global__ void pack_pos(const float* __restrict__ pos, float4* __restrict__ out, int n)
{
    int i = blockIdx.x * blockDim.x + threadIdx.x;
    if (i >= n) return;
    float x = pos[i * 3 + 0], y = pos[i * 3 + 1], z = pos[i * 3 + 2];
    out[i] = make_float4(x, y, z, x * x + y * y + z * z);
}

// ---------------- pack wq|wk|wv -> [L,128,384] ----------------
__global__ void pack_qkv(const float* __restrict__ wq, const float* __restrict__ wk,
                         const float* __restrict__ wv, float* __restrict__ out)
{
    int i = blockIdx.x * blockDim.x + threadIdx.x;
    if (i >= LTOT * ADIM * ADIM) return;
    int li = i / (ADIM * ADIM);
    int r = (i / ADIM) % ADIM;
    int c = i % ADIM;
    float* o = out + ((size_t)li * ADIM + r) * QKVS;
    o[c] = wq[i];
    o[ADIM + c] = wk[i];
    o[2 * ADIM + c] = wv[i];
}

// ---------------- strided copy of vox h0 into feat cols [0:128) ----------------
__global__ void copy_to_feat(const float* __restrict__ src, float* __restrict__ feat)
{
    int i = blockIdx.x * blockDim.x + threadIdx.x;
    if (i >= NV * ADIM) return;
    int r = i >> 7, c = i & 127;
    feat[(size_t)r * 640 + c] = src[i];
}

// ---------------- brute-force KNN: warp handles 2 dst, smem-tiled packed src
// fast path = single compare vs register 'last'; exact lexicographic insert in
// rare branch reproduces reference d2 = |a|^2+|b|^2-2ab and top_k stable order
template <int KK, bool EXCL>
__global__ __launch_bounds__(256, 2)
void knn_kernel(const float4* __restrict__ dpos4, const float4* __restrict__ spos4,
                int Ns, int* __restrict__ outIdx)
{
    const int TS = 1024;
    __shared__ float4 s4[TS];
    int lane = threadIdx.x & 31;
    int warp = threadIdx.x >> 5;
    int d0 = blockIdx.x * 16 + warp * 2;
    int d1 = d0 + 1;

    float4 p0 = dpos4[d0];
    float4 p1 = dpos4[d1];

    float bd0[KK], bd1[KK]; int bi0[KK], bi1[KK];
#pragma unroll
    for (int p = 0; p < KK; ++p) {
        bd0[p] = 3.0e38f; bi0[p] = 0x7fffffff;
        bd1[p] = 3.0e38f; bi1[p] = 0x7fffffff;
    }
    float last0 = 3.0e38f, last1 = 3.0e38f;

    for (int t0 = 0; t0 < Ns; t0 += TS) {
        int tn = Ns - t0; if (tn > TS) tn = TS;
        __syncthreads();
        for (int i = threadIdx.x; i < tn; i += 256) s4[i] = spos4[t0 + i];
        __syncthreads();
#pragma unroll 2
        for (int j = lane; j < tn; j += 32) {
            float4 qv = s4[j];
            int si = t0 + j;
            float dot0 = fmaf(p0.z, qv.z, fmaf(p0.y, qv.y, p0.x * qv.x));
            float d20 = (p0.w + qv.w) - 2.0f * dot0;
            float dot1 = fmaf(p1.z, qv.z, fmaf(p1.y, qv.y, p1.x * qv.x));
            float d21 = (p1.w + qv.w) - 2.0f * dot1;
            if (d20 <= last0 && !(EXCL && si == d0)) {
                if (d20 < bd0[KK - 1] || (d20 == bd0[KK - 1] && si < bi0[KK - 1])) {
                    bd0[KK - 1] = d20; bi0[KK - 1] = si;
#pragma unroll
                    for (int p = KK - 1; p > 0; --p) {
                        bool sw = (bd0[p] < bd0[p - 1]) || (bd0[p] == bd0[p - 1] && bi0[p] < bi0[p - 1]);
                        if (sw) {
                            float td = bd0[p]; bd0[p] = bd0[p - 1]; bd0[p - 1] = td;
                            int   ti = bi0[p]; bi0[p] = bi0[p - 1]; bi0[p - 1] = ti;
                        }
                    }
                    last0 = bd0[KK - 1];
                }
            }
            if (d21 <= last1 && !(EXCL && si == d1)) {
                if (d21 < bd1[KK - 1] || (d21 == bd1[KK - 1] && si < bi1[KK - 1])) {
                    bd1[KK - 1] = d21; bi1[KK - 1] = si;
#pragma unroll
                    for (int p = KK - 1; p > 0; --p) {
                        bool sw = (bd1[p] < bd1[p - 1]) || (bd1[p] == bd1[p - 1] && bi1[p] < bi1[p - 1]);
                        if (sw) {
                            float td = bd1[p]; bd1[p] = bd1[p - 1]; bd1[p - 1] = td;
                            int   ti = bi1[p]; bi1[p] = bi1[p - 1]; bi1[p - 1] = ti;
                        }
                    }
                    last1 = bd1[KK - 1];
                }
            }
        }
    }

    // warp merge of 32 sorted lane lists -> global KK smallest (lexicographic), per dst
    for (int r = 0; r < KK; ++r) {
        float cd = bd0[0]; int ci = bi0[0]; int cl = lane;
#pragma unroll
        for (int off = 16; off > 0; off >>= 1) {
            float od = __shfl_xor_sync(0xffffffffu, cd, off);
            int oi = __shfl_xor_sync(0xffffffffu, ci, off);
            int ol = __shfl_xor_sync(0xffffffffu, cl, off);
            if (od < cd || (od == cd && oi < ci)) { cd = od; ci = oi; cl = ol; }
        }
        if (lane == 0) outIdx[d0 * KK + r] = ci;
        if (lane == cl) {
#pragma unroll
            for (int p = 0; p < KK - 1; ++p) { bd0[p] = bd0[p + 1]; bi0[p] = bi0[p + 1]; }
            bd0[KK - 1] = 3.0e38f; bi0[KK - 1] = 0x7fffffff;
        }
    }
    for (int r = 0; r < KK; ++r) {
        float cd = bd1[0]; int ci = bi1[0]; int cl = lane;
#pragma unroll
        for (int off = 16; off > 0; off >>= 1) {
            float od = __shfl_xor_sync(0xffffffffu, cd, off);
            int oi = __shfl_xor_sync(0xffffffffu, ci, off);
            int ol = __shfl_xor_sync(0xffffffffu, cl, off);
            if (od < cd || (od == cd && oi < ci)) { cd = od; ci = oi; cl = ol; }
        }
        if (lane == 0) outIdx[d1 * KK + r] = ci;
        if (lane == cl) {
#pragma unroll
            for (int p = 0; p < KK - 1; ++p) { bd1[p] = bd1[p + 1]; bi1[p] = bi1[p + 1]; }
            bd1[KK - 1] = 3.0e38f; bi1[KK - 1] = 0x7fffffff;
        }
    }
}

// ---------------- per-row 128->8 projection (edge MLP first layer halves)
// warp per row; W is [128,8] row-major slice (row stride 8)
__global__ void proj8_kernel(const float* __restrict__ H, int Nrows,
                             const float* __restrict__ W, float* __restrict__ out)
{
    int w = (blockIdx.x * blockDim.x + threadIdx.x) >> 5;
    int lane = threadIdx.x & 31;
    if (w >= Nrows) return;
    const float* hr = H + (size_t)w * ADIM;
    float acc[8];
#pragma unroll
    for (int m = 0; m < 8; ++m) acc[m] = 0.f;
    for (int f = lane; f < ADIM; f += 32) {
        float hv = hr[f];
        const float* wr = W + f * 8;
#pragma unroll
        for (int m = 0; m < 8; ++m) acc[m] = fmaf(hv, wr[m], acc[m]);
    }
#pragma unroll
    for (int off = 16; off > 0; off >>= 1) {
#pragma unroll
        for (int m = 0; m < 8; ++m) acc[m] += __shfl_xor_sync(0xffffffffu, acc[m], off);
    }
    if (lane == 0) {
#pragma unroll
        for (int m = 0; m < 8; ++m) out[w * 8 + m] = acc[m];
    }
}

// ---------------- edge weight MLP (decomposed) + unified neighbor table write
__global__ void edgew_kernel(const int* __restrict__ nbr, int E, int Kk,
                             const float* __restrict__ dstPos, const float* __restrict__ srcPos,
                             const float* __restrict__ pSrc, const float* __restrict__ pDst,
                             const float* __restrict__ w1d, const float* __restrict__ b1,
                             const float* __restrict__ w2, const float* __restrict__ b2v,
                             int* __restrict__ Uidx, float* __restrict__ Uew,
                             int dstNodeBase, int slotOff, int srcGlobalOff)
{
    int e = blockIdx.x * blockDim.x + threadIdx.x;
    if (e >= E) return;
    int dl = e / Kk, slot = e - dl * Kk;
    int s = nbr[e];
    float dx = dstPos[dl * 3 + 0] - srcPos[s * 3 + 0];
    float dy = dstPos[dl * 3 + 1] - srcPos[s * 3 + 1];
    float dz = dstPos[dl * 3 + 2] - srcPos[s * 3 + 2];
    float ss = fmaf(dz, dz, fmaf(dy, dy, dx * dx));
    float d = sqrtf(ss + 1e-12f);
    float ew = b2v[0];
#pragma unroll
    for (int m = 0; m < 8; ++m) {
        float hmid = pSrc[s * 8 + m] + pDst[dl * 8 + m] + d * w1d[m] + b1[m];
        ew = fmaf(fmaxf(hmid, 0.f), w2[m], ew);
    }
    int un = dstNodeBase + dl;
    Uidx[un * MAXDEG + slotOff + slot] = srcGlobalOff + s;
    Uew[un * MAXDEG + slotOff + slot] = ew;
}

// ---------------- fused attention + residual + LayerNorm (+optional snapshot)
// one block (128 threads = 4 head-warps) per dst node; q|k|v packed row stride 384
__global__ void attn_kernel(const float* __restrict__ qkv,
                            const int* __restrict__ Uidx, const float* __restrict__ Uew,
                            float* __restrict__ h,
                            const float* __restrict__ lng, const float* __restrict__ lnb,
                            float* __restrict__ snap,   // stride 640 if non-null
                            int nodeBase)
{
    __shared__ float kvs[2 * MAXDEG][133];   // rows [0,deg): k, rows [MAXDEG,..): v
    __shared__ float qs[ADIM];
    __shared__ int   srcs[MAXDEG];
    __shared__ float ews[MAXDEG];
    __shared__ float red[8];

    int n = nodeBase + blockIdx.x;
    int t = threadIdx.x;
    int head = t >> 5, lane = t & 31;
    int deg = (n < NA) ? KAA : MAXDEG;

    if (t < deg) { srcs[t] = Uidx[n * MAXDEG + t]; ews[t] = Uew[n * MAXDEG + t]; }
    qs[t] = qkv[(size_t)n * QKVS + t];
    __syncthreads();

    // single staging pass: k and v rows of all neighbors (coalesced)
#pragma unroll 5
    for (int j = 0; j < deg; ++j) {
        const float* base = qkv + (size_t)srcs[j] * QKVS;
        kvs[j][t] = base[ADIM + t];
        kvs[MAXDEG + j][t] = base[2 * ADIM + t];
    }
    __syncthreads();

    // logits: lane j of each head-warp handles neighbor j
    float logit = -3.0e38f;
    if (lane < deg) {
        const float* kr = &kvs[lane][head << 5];
        const float* qr = &qs[head << 5];
        float acc = 0.f;
#pragma unroll
        for (int d = 0; d < 32; ++d) acc = fmaf(kr[d], qr[d], acc);
        logit = acc * 0.17677669529663687f + ews[lane];
    }
    float m = logit;
#pragma unroll
    for (int off = 16; off > 0; off >>= 1)
        m = fmaxf(m, __shfl_xor_sync(0xffffffffu, m, off));
    float z = (lane < deg) ? expf(logit - m) : 0.f;
    float ssum = z;
#pragma unroll
    for (int off = 16; off > 0; off >>= 1)
        ssum += __shfl_xor_sync(0xffffffffu, ssum, off);
    float alpha = z / (ssum + 1e-9f);

    float acc = 0.f;
    for (int j = 0; j < deg; ++j) {
        float a = __shfl_sync(0xffffffffu, alpha, j);
        acc = fmaf(a, kvs[MAXDEG + j][(head << 5) + lane], acc);
    }

    // residual + LN
    float y = h[(size_t)n * ADIM + t] + acc;
    float s1 = y, s2 = y * y;
#pragma unroll
    for (int off = 16; off > 0; off >>= 1) {
        s1 += __shfl_xor_sync(0xffffffffu, s1, off);
        s2 += __shfl_xor_sync(0xffffffffu, s2, off);
    }
    if (lane == 0) { red[head] = s1; red[4 + head] = s2; }
    __syncthreads();
    float t1 = red[0] + red[1] + red[2] + red[3];
    float t2 = red[4] + red[5] + red[6] + red[7];
    float mu = t1 * (1.0f / ADIM);
    float var = fmaxf(t2 * (1.0f / ADIM) - mu * mu, 0.f);
    float outv = (y - mu) * rsqrtf(var + 1e-5f) * lng[t] + lnb[t];
    h[(size_t)n * ADIM + t] = outv;
    if (snap != nullptr && n >= NA) snap[(size_t)(n - NA) * 640 + t] = outv;
}

// ---------------- host ----------------
extern "C" void kernel_launch(void* const* d_in, const int* in_sizes, int n_in,
                              void* d_out, int out_size)
{
    const float* atom_x    = (const float*)d_in[0];
    const float* atom_pos  = (const float*)d_in[1];
    const float* vox_x     = (const float*)d_in[2];
    const float* vox_pos   = (const float*)d_in[3];
    const float* w_atom_in = (const float*)d_in[4];
    const float* b_atom_in = (const float*)d_in[5];
    const float* w_vox_in  = (const float*)d_in[6];
    const float* b_vox_in  = (const float*)d_in[7];
    const float* aa_w1 = (const float*)d_in[8];
    const float* aa_b1 = (const float*)d_in[9];
    const float* aa_w2 = (const float*)d_in[10];
    const float* aa_b2 = (const float*)d_in[11];
    const float* av_w1 = (const float*)d_in[12];
    const float* av_b1 = (const float*)d_in[13];
    const float* av_w2 = (const float*)d_in[14];
    const float* av_b2 = (const float*)d_in[15];
    const float* vv_w1 = (const float*)d_in[16];
    const float* vv_b1 = (const float*)d_in[17];
    const float* vv_w2 = (const float*)d_in[18];
    const float* vv_b2 = (const float*)d_in[19];
    const float* wq   = (const float*)d_in[20];
    const float* wk   = (const float*)d_in[21];
    const float* wv   = (const float*)d_in[22];
    const float* ln_g = (const float*)d_in[23];
    const float* ln_b = (const float*)d_in[24];
    const float* w_o1 = (const float*)d_in[25];
    const float* b_o1 = (const float*)d_in[26];
    const float* w_o2 = (const float*)d_in[27];
    const float* b_o2 = (const float*)d_in[28];
    float* out = (float*)d_out;
    (void)in_sizes; (void)n_in; (void)out_size;

    float *h, *qkv, *wqkv, *Uew, *paas, *paad, *pavd, *pavs, *pvvs, *pvvd, *feat, *hidden;
    float4 *apos4, *vpos4;
    int *aaIdx, *avIdx, *vvIdx, *Uidx;
    cudaGetSymbolAddress((void**)&h, g_h);
    cudaGetSymbolAddress((void**)&qkv, g_qkv);
    cudaGetSymbolAddress((void**)&wqkv, g_wqkv);
    cudaGetSymbolAddress((void**)&apos4, g_apos4);
    cudaGetSymbolAddress((void**)&vpos4, g_vpos4);
    cudaGetSymbolAddress((void**)&aaIdx, g_aa);
    cudaGetSymbolAddress((void**)&avIdx, g_av);
    cudaGetSymbolAddress((void**)&vvIdx, g_vv);
    cudaGetSymbolAddress((void**)&Uidx, g_Uidx);
    cudaGetSymbolAddress((void**)&Uew, g_Uew);
    cudaGetSymbolAddress((void**)&paas, g_paas);
    cudaGetSymbolAddress((void**)&paad, g_paad);
    cudaGetSymbolAddress((void**)&pavd, g_pavd);
    cudaGetSymbolAddress((void**)&pavs, g_pavs);
    cudaGetSymbolAddress((void**)&pvvs, g_pvvs);
    cudaGetSymbolAddress((void**)&pvvd, g_pvvd);
    cudaGetSymbolAddress((void**)&feat, g_feat);
    cudaGetSymbolAddress((void**)&hidden, g_hidden);

    const float* voxh0 = h + (size_t)NA * ADIM;   // valid until layer loop mutates h

    // 0) packing
    pack_pos<<<(NA + 255) / 256, 256>>>(atom_pos, apos4, NA);
    pack_pos<<<(NV + 255) / 256, 256>>>(vox_pos, vpos4, NV);
    pack_qkv<<<(LTOT * ADIM * ADIM + 255) / 256, 256>>>(wq, wk, wv, wqkv);

    // 1) input projections -> h (atoms then voxels); stash vox_h0 into feat[:,0:128]
    gemm64<<<dim3(NA / 64, ADIM / 64), 256>>>(atom_x, w_atom_in, b_atom_in, h, FDIM, ADIM, 0, ADIM);
    gemm64<<<dim3(NV / 64, ADIM / 64), 256>>>(vox_x, w_vox_in, b_vox_in, (float*)voxh0, FDIM, ADIM, 0, ADIM);
    copy_to_feat<<<(NV * ADIM + 255) / 256, 256>>>(voxh0, feat);

    // 2) KNN graphs (2 dst per warp, 16 dst per block)
    knn_kernel<KAA, true><<<NA / 16, 256>>>(apos4, apos4, NA, aaIdx);
    knn_kernel<KVV, false><<<NV / 16, 256>>>(vpos4, apos4, NA, avIdx);
    knn_kernel<KVV, true><<<NV / 16, 256>>>(vpos4, vpos4, NV, vvIdx);

    // 3) edge-MLP first-layer projections (top half of W1 = i0 features, bottom = i1)
    proj8_kernel<<<NA / 8, 256>>>(h, NA, aa_w1, paas);                 // aa: i0 = src atom
    proj8_kernel<<<NA / 8, 256>>>(h, NA, aa_w1 + 128 * 8, paad);       // aa: i1 = dst atom
    proj8_kernel<<<NV / 8, 256>>>(voxh0, NV, av_w1, pavd);             // av: i0 = vox (dst)
    proj8_kernel<<<NA / 8, 256>>>(h, NA, av_w1 + 128 * 8, pavs);       // av: i1 = atom (src)
    proj8_kernel<<<NV / 8, 256>>>(voxh0, NV, vv_w1, pvvs);             // vv: i0 = src vox
    proj8_kernel<<<NV / 8, 256>>>(voxh0, NV, vv_w1 + 128 * 8, pvvd);   // vv: i1 = dst vox

    // 4) edge weights + unified neighbor table
    edgew_kernel<<<(NA * KAA + 255) / 256, 256>>>(aaIdx, NA * KAA, KAA, atom_pos, atom_pos,
        paas, paad, aa_w1 + 256 * 8, aa_b1, aa_w2, aa_b2, Uidx, Uew, 0, 0, 0);
    edgew_kernel<<<(NV * KVV + 255) / 256, 256>>>(avIdx, NV * KVV, KVV, vox_pos, atom_pos,
        pavs, pavd, av_w1 + 256 * 8, av_b1, av_w2, av_b2, Uidx, Uew, NA, 0, 0);
    edgew_kernel<<<(NV * KVV + 255) / 256, 256>>>(vvIdx, NV * KVV, KVV, vox_pos, vox_pos,
        pvvs, pvvd, vv_w1 + 256 * 8, vv_b1, vv_w2, vv_b2, Uidx, Uew, NA, KVV, NA);

    // 5) attention stack (8 layers), fused QKV GEMM, snapshot vox rows into feat.
    //    Last layer: only vox nodes matter (atom h is never read again).
    for (int li = 0; li < LTOT; ++li) {
        gemm64<<<dim3(NN / 64, QKVS / 64), 256>>>(h, wqkv + (size_t)li * ADIM * QKVS,
                                                  nullptr, qkv, ADIM, QKVS, 0, QKVS);
        float* snap = (li & 1) ? (feat + (size_t)((li >> 1) + 1) * ADIM) : nullptr;
        if (li == LTOT - 1) {
            attn_kernel<<<NV, 128>>>(qkv, Uidx, Uew, h,
                                     ln_g + (size_t)li * ADIM, ln_b + (size_t)li * ADIM, snap, NA);
        } else {
            attn_kernel<<<NN, 128>>>(qkv, Uidx, Uew, h,
                                     ln_g + (size_t)li * ADIM, ln_b + (size_t)li * ADIM, snap, 0);
        }
    }

    // 6) output head: feat [NV,640] -> relu -> [NV,128] -> [NV,128]
    gemm64<<<dim3(NV / 64, ADIM / 64), 256>>>(feat, w_o1, b_o1, hidden, 640, ADIM, 1, ADIM);
    gemm64<<<dim3(NV / 64, OUTD / 64), 256>>>(hidden, w_o2, b_o2, out, ADIM, OUTD, 0, OUTD);
}

// round 10
// speedup vs baseline: 1.4552x; 1.4552x over previous
#include <cuda_runtime.h>
#include <math.h>

#define NA 8192
#define NV 4096
#define NN 12288      // NA + NV
#define FDIM 64
#define ADIM 128
#define QKVS 384
#define KAA 10
#define KVV 15
#define MAXDEG 30
#define LTOT 8
#define OUTD 128

// ---------------- device scratch (no allocations allowed) ----------------
__device__ float  g_h[NN * ADIM];
__device__ float  g_qkv[NN * QKVS];
__device__ float  g_wqkv[LTOT * ADIM * QKVS];
__device__ float4 g_apos4[NA];
__device__ float4 g_vpos4[NV];
__device__ int    g_aa[NA * KAA];
__device__ int    g_av[NV * KVV];
__device__ int    g_vv[NV * KVV];
__device__ int    g_Uidx[NN * MAXDEG];
__device__ float  g_Uew[NN * MAXDEG];
__device__ float  g_paas[NA * 8];
__device__ float  g_paad[NA * 8];
__device__ float  g_pavd[NV * 8];
__device__ float  g_pavs[NA * 8];
__device__ float  g_pvvs[NV * 8];
__device__ float  g_pvvd[NV * 8];
__device__ float  g_feat[NV * 640];
__device__ float  g_hidden[NV * ADIM];

// ---------------- big-tile GEMM: C[M,N] = A[M,K] @ B[K,N] (+bias)(+relu)
// grid = (M/128, N/128), 256 threads, 8x8 outputs per thread, BK=8
__global__ __launch_bounds__(256)
void gemm128(const float* __restrict__ A, const float* __restrict__ B,
             const float* __restrict__ bias, float* __restrict__ C,
             int K, int N, int doRelu, int ldc)
{
    __shared__ __align__(16) float As[8][128];
    __shared__ __align__(16) float Bs[8][128];
    int tid = threadIdx.x;
    int bm = blockIdx.x << 7, bn = blockIdx.y << 7;
    int arow = tid >> 1, acol = (tid & 1) << 2;
    int brow = tid >> 5, bcol = (tid & 31) << 2;
    int tx = tid & 15, ty = tid >> 4;

    const float* Ap = A + (size_t)(bm + arow) * K + acol;
    const float* Bp = B + (size_t)brow * N + bn + bcol;

    float acc[8][8];
#pragma unroll
    for (int i = 0; i < 8; ++i)
#pragma unroll
        for (int j = 0; j < 8; ++j) acc[i][j] = 0.f;

    float ar[8], br[8];
    for (int k0 = 0; k0 < K; k0 += 8) {
        float4 av = *(const float4*)(Ap + k0);
        float4 bv = *(const float4*)(Bp + (size_t)k0 * N);
        As[acol + 0][arow] = av.x;
        As[acol + 1][arow] = av.y;
        As[acol + 2][arow] = av.z;
        As[acol + 3][arow] = av.w;
        *(float4*)&Bs[brow][bcol] = bv;
        __syncthreads();
#pragma unroll
        for (int kk = 0; kk < 8; ++kk) {
            *(float4*)&ar[0] = *(const float4*)&As[kk][ty << 3];
            *(float4*)&ar[4] = *(const float4*)&As[kk][(ty << 3) + 4];
            *(float4*)&br[0] = *(const float4*)&Bs[kk][tx << 3];
            *(float4*)&br[4] = *(const float4*)&Bs[kk][(tx << 3) + 4];
#pragma unroll
            for (int i = 0; i < 8; ++i)
#pragma unroll
                for (int j = 0; j < 8; ++j)
                    acc[i][j] = fmaf(ar[i], br[j], acc[i][j]);
        }
        __syncthreads();
    }

#pragma unroll
    for (int i = 0; i < 8; ++i) {
        int r = bm + (ty << 3) + i;
        float* Cr = C + (size_t)r * ldc + bn + (tx << 3);
#pragma unroll
        for (int j = 0; j < 8; ++j) {
            float vv = acc[i][j];
            if (bias) vv += bias[bn + (tx << 3) + j];
            if (doRelu) vv = fmaxf(vv, 0.f);
            Cr[j] = vv;
        }
    }
}

// ---------------- position packing: (x, y, z, |p|^2) ----------------
__global__ void pack_pos(const float* __restrict__ pos, float4* __restrict__ out, int n)
{
    int i = blockIdx.x * blockDim.x + threadIdx.x;
    if (i >= n) return;
    float x = pos[i * 3 + 0], y = pos[i * 3 + 1], z = pos[i * 3 + 2];
    out[i] = make_float4(x, y, z, x * x + y * y + z * z);
}

// ---------------- pack wq|wk|wv -> [L,128,384] ----------------
__global__ void pack_qkv(const float* __restrict__ wq, const float* __restrict__ wk,
                         const float* __restrict__ wv, float* __restrict__ out)
{
    int i = blockIdx.x * blockDim.x + threadIdx.x;
    if (i >= LTOT * ADIM * ADIM) return;
    int li = i / (ADIM * ADIM);
    int r = (i / ADIM) % ADIM;
    int c = i % ADIM;
    float* o = out + ((size_t)li * ADIM + r) * QKVS;
    o[c] = wq[i];
    o[ADIM + c] = wk[i];
    o[2 * ADIM + c] = wv[i];
}

// ---------------- strided copy of vox h0 into feat cols [0:128) ----------------
__global__ void copy_to_feat(const float* __restrict__ src, float* __restrict__ feat)
{
    int i = blockIdx.x * blockDim.x + threadIdx.x;
    if (i >= NV * ADIM) return;
    int r = i >> 7, c = i & 127;
    feat[(size_t)r * 640 + c] = src[i];
}

// ---------------- warp-cooperative brute-force KNN ----------------
// One warp per dst. The top-K list is DISTRIBUTED across lanes: lane j holds the
// j-th smallest (d2, idx) in exact lexicographic order (== jax top_k stable
// tie-break). Candidates passing the warp threshold (lane KK-1's element) are
// found by ballot and inserted with a whole-warp shuffle-up insert — no
// divergent per-lane insertion sort. d2 = |a|^2 + |b|^2 - 2 a.b exactly as ref.
template <int KK, bool EXCL>
__global__ __launch_bounds__(256)
void knn_warp(const float4* __restrict__ dpos4, const float4* __restrict__ spos4,
              int Ns, int* __restrict__ outIdx)
{
    const int TS = 1024;
    const unsigned FULL = 0xffffffffu;
    __shared__ float4 s4[TS];
    int lane = threadIdx.x & 31;
    int warp = threadIdx.x >> 5;
    int dst = blockIdx.x * 8 + warp;

    float4 p = dpos4[dst];

    // distributed sorted list (lanes >= KK hold overflow/garbage, never read back)
    float ld = __int_as_float(0x7f800000);  // +inf
    int   li = 0x7fffffff;
    float T  = ld;     // list[KK-1].d
    int   Ti = li;     // list[KK-1].i

    for (int t0 = 0; t0 < Ns; t0 += TS) {
        int tn = Ns - t0; if (tn > TS) tn = TS;
        __syncthreads();
        for (int i = threadIdx.x; i < tn; i += 256) s4[i] = spos4[t0 + i];
        __syncthreads();
        for (int j = lane; j < tn; j += 32) {
            int si = t0 + j;
            float4 qv = s4[j];
            float dot = fmaf(p.z, qv.z, fmaf(p.y, qv.y, p.x * qv.x));
            float d2 = (p.w + qv.w) - 2.0f * dot;
            if (EXCL && si == dst) { d2 = __int_as_float(0x7f800000); si = 0x7fffffff; }
            bool pass = (d2 < T) || (d2 == T && si < Ti);
            unsigned m = __ballot_sync(FULL, pass);
            while (m) {
                int s = __ffs(m) - 1;
                float cd = __shfl_sync(FULL, d2, s);
                int   ci = __shfl_sync(FULL, si, s);
                // warp-cooperative sorted insert
                bool before = (cd < ld) || (cd == ld && ci < li);
                unsigned bm = __ballot_sync(FULL, before);
                float ud = __shfl_up_sync(FULL, ld, 1);
                int   ui = __shfl_up_sync(FULL, li, 1);
                int firstBefore = __ffs(bm) - 1;   // bm != 0: lane KK-1 always 'before'
                if (before) {
                    if (lane == firstBefore) { ld = cd; li = ci; }
                    else                     { ld = ud; li = ui; }
                }
                T  = __shfl_sync(FULL, ld, KK - 1);
                Ti = __shfl_sync(FULL, li, KK - 1);
                pass = pass && (lane > s) && ((d2 < T) || (d2 == T && si < Ti));
                m = __ballot_sync(FULL, pass);
            }
        }
    }
    if (lane < KK) outIdx[dst * KK + lane] = li;
}

// ---------------- per-row 128->8 projection (edge MLP first layer halves)
__global__ void proj8_kernel(const float* __restrict__ H, int Nrows,
                             const float* __restrict__ W, float* __restrict__ out)
{
    int w = (blockIdx.x * blockDim.x + threadIdx.x) >> 5;
    int lane = threadIdx.x & 31;
    if (w >= Nrows) return;
    const float* hr = H + (size_t)w * ADIM;
    float acc[8];
#pragma unroll
    for (int m = 0; m < 8; ++m) acc[m] = 0.f;
    for (int f = lane; f < ADIM; f += 32) {
        float hv = hr[f];
        const float* wr = W + f * 8;
#pragma unroll
        for (int m = 0; m < 8; ++m) acc[m] = fmaf(hv, wr[m], acc[m]);
    }
#pragma unroll
    for (int off = 16; off > 0; off >>= 1) {
#pragma unroll
        for (int m = 0; m < 8; ++m) acc[m] += __shfl_xor_sync(0xffffffffu, acc[m], off);
    }
    if (lane == 0) {
#pragma unroll
        for (int m = 0; m < 8; ++m) out[w * 8 + m] = acc[m];
    }
}

// ---------------- edge weight MLP (decomposed) + unified neighbor table write
__global__ void edgew_kernel(const int* __restrict__ nbr, int E, int Kk,
                             const float* __restrict__ dstPos, const float* __restrict__ srcPos,
                             const float* __restrict__ pSrc, const float* __restrict__ pDst,
                             const float* __restrict__ w1d, const float* __restrict__ b1,
                             const float* __restrict__ w2, const float* __restrict__ b2v,
                             int* __restrict__ Uidx, float* __restrict__ Uew,
                             int dstNodeBase, int slotOff, int srcGlobalOff)
{
    int e = blockIdx.x * blockDim.x + threadIdx.x;
    if (e >= E) return;
    int dl = e / Kk, slot = e - dl * Kk;
    int s = nbr[e];
    float dx = dstPos[dl * 3 + 0] - srcPos[s * 3 + 0];
    float dy = dstPos[dl * 3 + 1] - srcPos[s * 3 + 1];
    float dz = dstPos[dl * 3 + 2] - srcPos[s * 3 + 2];
    float ss = fmaf(dz, dz, fmaf(dy, dy, dx * dx));
    float d = sqrtf(ss + 1e-12f);
    float ew = b2v[0];
#pragma unroll
    for (int m = 0; m < 8; ++m) {
        float hmid = pSrc[s * 8 + m] + pDst[dl * 8 + m] + d * w1d[m] + b1[m];
        ew = fmaf(fmaxf(hmid, 0.f), w2[m], ew);
    }
    int un = dstNodeBase + dl;
    Uidx[un * MAXDEG + slotOff + slot] = srcGlobalOff + s;
    Uew[un * MAXDEG + slotOff + slot] = ew;
}

// ---------------- fused attention + residual + LayerNorm (+optional snapshot)
// one block (128 threads = 4 head-warps) per dst node; q|k|v packed row stride 384
__global__ void attn_kernel(const float* __restrict__ qkv,
                            const int* __restrict__ Uidx, const float* __restrict__ Uew,
                            float* __restrict__ h,
                            const float* __restrict__ lng, const float* __restrict__ lnb,
                            float* __restrict__ snap,   // stride 640 if non-null
                            int nodeBase)
{
    __shared__ float kvs[2 * MAXDEG][133];   // rows [0,deg): k, rows [MAXDEG,..): v
    __shared__ float qs[ADIM];
    __shared__ int   srcs[MAXDEG];
    __shared__ float ews[MAXDEG];
    __shared__ float red[8];

    int n = nodeBase + blockIdx.x;
    int t = threadIdx.x;
    int head = t >> 5, lane = t & 31;
    int deg = (n < NA) ? KAA : MAXDEG;

    if (t < deg) { srcs[t] = Uidx[n * MAXDEG + t]; ews[t] = Uew[n * MAXDEG + t]; }
    qs[t] = qkv[(size_t)n * QKVS + t];
    __syncthreads();

    // single staging pass: k and v rows of all neighbors (coalesced)
#pragma unroll 5
    for (int j = 0; j < deg; ++j) {
        const float* base = qkv + (size_t)srcs[j] * QKVS;
        kvs[j][t] = base[ADIM + t];
        kvs[MAXDEG + j][t] = base[2 * ADIM + t];
    }
    __syncthreads();

    // logits: lane j of each head-warp handles neighbor j
    float logit = -3.0e38f;
    if (lane < deg) {
        const float* kr = &kvs[lane][head << 5];
        const float* qr = &qs[head << 5];
        float acc = 0.f;
#pragma unroll
        for (int d = 0; d < 32; ++d) acc = fmaf(kr[d], qr[d], acc);
        logit = acc * 0.17677669529663687f + ews[lane];
    }
    float m = logit;
#pragma unroll
    for (int off = 16; off > 0; off >>= 1)
        m = fmaxf(m, __shfl_xor_sync(0xffffffffu, m, off));
    float z = (lane < deg) ? expf(logit - m) : 0.f;
    float ssum = z;
#pragma unroll
    for (int off = 16; off > 0; off >>= 1)
        ssum += __shfl_xor_sync(0xffffffffu, ssum, off);
    float alpha = z / (ssum + 1e-9f);

    float acc = 0.f;
    for (int j = 0; j < deg; ++j) {
        float a = __shfl_sync(0xffffffffu, alpha, j);
        acc = fmaf(a, kvs[MAXDEG + j][(head << 5) + lane], acc);
    }

    // residual + LN
    float y = h[(size_t)n * ADIM + t] + acc;
    float s1 = y, s2 = y * y;
#pragma unroll
    for (int off = 16; off > 0; off >>= 1) {
        s1 += __shfl_xor_sync(0xffffffffu, s1, off);
        s2 += __shfl_xor_sync(0xffffffffu, s2, off);
    }
    if (lane == 0) { red[head] = s1; red[4 + head] = s2; }
    __syncthreads();
    float t1 = red[0] + red[1] + red[2] + red[3];
    float t2 = red[4] + red[5] + red[6] + red[7];
    float mu = t1 * (1.0f / ADIM);
    float var = fmaxf(t2 * (1.0f / ADIM) - mu * mu, 0.f);
    float outv = (y - mu) * rsqrtf(var + 1e-5f) * lng[t] + lnb[t];
    h[(size_t)n * ADIM + t] = outv;
    if (snap != nullptr && n >= NA) snap[(size_t)(n - NA) * 640 + t] = outv;
}

// ---------------- host ----------------
extern "C" void kernel_launch(void* const* d_in, const int* in_sizes, int n_in,
                              void* d_out, int out_size)
{
    const float* atom_x    = (const float*)d_in[0];
    const float* atom_pos  = (const float*)d_in[1];
    const float* vox_x     = (const float*)d_in[2];
    const float* vox_pos   = (const float*)d_in[3];
    const float* w_atom_in = (const float*)d_in[4];
    const float* b_atom_in = (const float*)d_in[5];
    const float* w_vox_in  = (const float*)d_in[6];
    const float* b_vox_in  = (const float*)d_in[7];
    const float* aa_w1 = (const float*)d_in[8];
    const float* aa_b1 = (const float*)d_in[9];
    const float* aa_w2 = (const float*)d_in[10];
    const float* aa_b2 = (const float*)d_in[11];
    const float* av_w1 = (const float*)d_in[12];
    const float* av_b1 = (const float*)d_in[13];
    const float* av_w2 = (const float*)d_in[14];
    const float* av_b2 = (const float*)d_in[15];
    const float* vv_w1 = (const float*)d_in[16];
    const float* vv_b1 = (const float*)d_in[17];
    const float* vv_w2 = (const float*)d_in[18];
    const float* vv_b2 = (const float*)d_in[19];
    const float* wq   = (const float*)d_in[20];
    const float* wk   = (const float*)d_in[21];
    const float* wv   = (const float*)d_in[22];
    const float* ln_g = (const float*)d_in[23];
    const float* ln_b = (const float*)d_in[24];
    const float* w_o1 = (const float*)d_in[25];
    const float* b_o1 = (const float*)d_in[26];
    const float* w_o2 = (const float*)d_in[27];
    const float* b_o2 = (const float*)d_in[28];
    float* out = (float*)d_out;
    (void)in_sizes; (void)n_in; (void)out_size;

    float *h, *qkv, *wqkv, *Uew, *paas, *paad, *pavd, *pavs, *pvvs, *pvvd, *feat, *hidden;
    float4 *apos4, *vpos4;
    int *aaIdx, *avIdx, *vvIdx, *Uidx;
    cudaGetSymbolAddress((void**)&h, g_h);
    cudaGetSymbolAddress((void**)&qkv, g_qkv);
    cudaGetSymbolAddress((void**)&wqkv, g_wqkv);
    cudaGetSymbolAddress((void**)&apos4, g_apos4);
    cudaGetSymbolAddress((void**)&vpos4, g_vpos4);
    cudaGetSymbolAddress((void**)&aaIdx, g_aa);
    cudaGetSymbolAddress((void**)&avIdx, g_av);
    cudaGetSymbolAddress((void**)&vvIdx, g_vv);
    cudaGetSymbolAddress((void**)&Uidx, g_Uidx);
    cudaGetSymbolAddress((void**)&Uew, g_Uew);
    cudaGetSymbolAddress((void**)&paas, g_paas);
    cudaGetSymbolAddress((void**)&paad, g_paad);
    cudaGetSymbolAddress((void**)&pavd, g_pavd);
    cudaGetSymbolAddress((void**)&pavs, g_pavs);
    cudaGetSymbolAddress((void**)&pvvs, g_pvvs);
    cudaGetSymbolAddress((void**)&pvvd, g_pvvd);
    cudaGetSymbolAddress((void**)&feat, g_feat);
    cudaGetSymbolAddress((void**)&hidden, g_hidden);

    const float* voxh0 = h + (size_t)NA * ADIM;   // valid until layer loop mutates h

    // 0) packing
    pack_pos<<<(NA + 255) / 256, 256>>>(atom_pos, apos4, NA);
    pack_pos<<<(NV + 255) / 256, 256>>>(vox_pos, vpos4, NV);
    pack_qkv<<<(LTOT * ADIM * ADIM + 255) / 256, 256>>>(wq, wk, wv, wqkv);

    // 1) input projections -> h (atoms then voxels); stash vox_h0 into feat[:,0:128]
    gemm128<<<dim3(NA / 128, ADIM / 128), 256>>>(atom_x, w_atom_in, b_atom_in, h, FDIM, ADIM, 0, ADIM);
    gemm128<<<dim3(NV / 128, ADIM / 128), 256>>>(vox_x, w_vox_in, b_vox_in, (float*)voxh0, FDIM, ADIM, 0, ADIM);
    copy_to_feat<<<(NV * ADIM + 255) / 256, 256>>>(voxh0, feat);

    // 2) KNN graphs (warp-cooperative top-K, 8 dst per block)
    knn_warp<KAA, true><<<NA / 8, 256>>>(apos4, apos4, NA, aaIdx);
    knn_warp<KVV, false><<<NV / 8, 256>>>(vpos4, apos4, NA, avIdx);
    knn_warp<KVV, true><<<NV / 8, 256>>>(vpos4, vpos4, NV, vvIdx);

    // 3) edge-MLP first-layer projections (top half of W1 = i0 features, bottom = i1)
    proj8_kernel<<<NA / 8, 256>>>(h, NA, aa_w1, paas);                 // aa: i0 = src atom
    proj8_kernel<<<NA / 8, 256>>>(h, NA, aa_w1 + 128 * 8, paad);       // aa: i1 = dst atom
    proj8_kernel<<<NV / 8, 256>>>(voxh0, NV, av_w1, pavd);             // av: i0 = vox (dst)
    proj8_kernel<<<NA / 8, 256>>>(h, NA, av_w1 + 128 * 8, pavs);       // av: i1 = atom (src)
    proj8_kernel<<<NV / 8, 256>>>(voxh0, NV, vv_w1, pvvs);             // vv: i0 = src vox
    proj8_kernel<<<NV / 8, 256>>>(voxh0, NV, vv_w1 + 128 * 8, pvvd);   // vv: i1 = dst vox

    // 4) edge weights + unified neighbor table
    edgew_kernel<<<(NA * KAA + 255) / 256, 256>>>(aaIdx, NA * KAA, KAA, atom_pos, atom_pos,
        paas, paad, aa_w1 + 256 * 8, aa_b1, aa_w2, aa_b2, Uidx, Uew, 0, 0, 0);
    edgew_kernel<<<(NV * KVV + 255) / 256, 256>>>(avIdx, NV * KVV, KVV, vox_pos, atom_pos,
        pavs, pavd, av_w1 + 256 * 8, av_b1, av_w2, av_b2, Uidx, Uew, NA, 0, 0);
    edgew_kernel<<<(NV * KVV + 255) / 256, 256>>>(vvIdx, NV * KVV, KVV, vox_pos, vox_pos,
        pvvs, pvvd, vv_w1 + 256 * 8, vv_b1, vv_w2, vv_b2, Uidx, Uew, NA, KVV, NA);

    // 5) attention stack (8 layers), fused QKV GEMM, snapshot vox rows into feat.
    //    Last layer: only vox nodes matter (atom h is never read again; atom k/v
    //    still computed by the full-height GEMM since vox neighbors include atoms).
    for (int li = 0; li < LTOT; ++li) {
        gemm128<<<dim3(NN / 128, QKVS / 128), 256>>>(h, wqkv + (size_t)li * ADIM * QKVS,
                                                     nullptr, qkv, ADIM, QKVS, 0, QKVS);
        float* snap = (li & 1) ? (feat + (size_t)((li >> 1) + 1) * ADIM) : nullptr;
        if (li == LTOT - 1) {
            attn_kernel<<<NV, 128>>>(qkv, Uidx, Uew, h,
                                     ln_g + (size_t)li * ADIM, ln_b + (size_t)li * ADIM, snap, NA);
        } else {
            attn_kernel<<<NN, 128>>>(qkv, Uidx, Uew, h,
                                     ln_g + (size_t)li * ADIM, ln_b + (size_t)li * ADIM, snap, 0);
        }
    }

    // 6) output head: feat [NV,640] -> relu -> [NV,128] -> [NV,128]
    gemm128<<<dim3(NV / 128, ADIM / 128), 256>>>(feat, w_o1, b_o1, hidden, 640, ADIM, 1, ADIM);
    gemm128<<<dim3(NV / 128, OUTD / 128), 256>>>(hidden, w_o2, b_o2, out, ADIM, OUTD, 0, OUTD);
}

// round 11
// speedup vs baseline: 2.0207x; 1.3886x over previous
#include <cuda_runtime.h>
#include <math.h>

#define NA 8192
#define NV 4096
#define NN 12288      // NA + NV
#define FDIM 64
#define ADIM 128
#define QKVS 384
#define KAA 10
#define KVV 15
#define MAXDEG 30
#define LTOT 8
#define OUTD 128

// ---------------- device scratch (no allocations allowed) ----------------
__device__ float  g_h[NN * ADIM];
__device__ float  g_qkv[NN * QKVS];
__device__ float  g_wqkv[LTOT * ADIM * QKVS];
__device__ float4 g_apos4[NA];
__device__ float4 g_vpos4[NV];
__device__ int    g_aa[NA * KAA];
__device__ int    g_av[NV * KVV];
__device__ int    g_vv[NV * KVV];
__device__ int    g_Uidx[NN * MAXDEG];
__device__ float  g_Uew[NN * MAXDEG];
__device__ float  g_paas[NA * 8];
__device__ float  g_paad[NA * 8];
__device__ float  g_pavd[NV * 8];
__device__ float  g_pavs[NA * 8];
__device__ float  g_pvvs[NV * 8];
__device__ float  g_pvvd[NV * 8];
__device__ float  g_feat[NV * 640];
__device__ float  g_hidden[NV * ADIM];

// ---------------- double-buffered big-tile GEMM ----------------
// C[M,N] = A[M,K] @ B[K,N] (+bias)(+relu); grid=(M/128,N/128), 256 thr, 8x8/thr
__global__ __launch_bounds__(256, 2)
void gemm128(const float* __restrict__ A, const float* __restrict__ B,
             const float* __restrict__ bias, float* __restrict__ C,
             int K, int N, int doRelu, int ldc)
{
    __shared__ __align__(16) float As[2][8][128];
    __shared__ __align__(16) float Bs[2][8][128];
    int tid = threadIdx.x;
    int bm = blockIdx.x << 7, bn = blockIdx.y << 7;
    int arow = tid >> 1, acol = (tid & 1) << 2;
    int brow = tid >> 5, bcol = (tid & 31) << 2;
    int tx = tid & 15, ty = tid >> 4;

    const float* Ap = A + (size_t)(bm + arow) * K + acol;
    const float* Bp = B + (size_t)brow * N + bn + bcol;

    float acc[8][8];
#pragma unroll
    for (int i = 0; i < 8; ++i)
#pragma unroll
        for (int j = 0; j < 8; ++j) acc[i][j] = 0.f;

    // preload tile 0
    {
        float4 av = *(const float4*)(Ap);
        float4 bv = *(const float4*)(Bp);
        As[0][acol + 0][arow] = av.x;
        As[0][acol + 1][arow] = av.y;
        As[0][acol + 2][arow] = av.z;
        As[0][acol + 3][arow] = av.w;
        *(float4*)&Bs[0][brow][bcol] = bv;
    }
    __syncthreads();

    int buf = 0;
    for (int k0 = 0; k0 < K; k0 += 8) {
        bool more = (k0 + 8) < K;
        float4 av2, bv2;
        if (more) {
            av2 = *(const float4*)(Ap + k0 + 8);
            bv2 = *(const float4*)(Bp + (size_t)(k0 + 8) * N);
        }
        float ar[8], br[8];
#pragma unroll
        for (int kk = 0; kk < 8; ++kk) {
            *(float4*)&ar[0] = *(const float4*)&As[buf][kk][ty << 3];
            *(float4*)&ar[4] = *(const float4*)&As[buf][kk][(ty << 3) + 4];
            *(float4*)&br[0] = *(const float4*)&Bs[buf][kk][tx << 3];
            *(float4*)&br[4] = *(const float4*)&Bs[buf][kk][(tx << 3) + 4];
#pragma unroll
            for (int i = 0; i < 8; ++i)
#pragma unroll
                for (int j = 0; j < 8; ++j)
                    acc[i][j] = fmaf(ar[i], br[j], acc[i][j]);
        }
        if (more) {
            As[buf ^ 1][acol + 0][arow] = av2.x;
            As[buf ^ 1][acol + 1][arow] = av2.y;
            As[buf ^ 1][acol + 2][arow] = av2.z;
            As[buf ^ 1][acol + 3][arow] = av2.w;
            *(float4*)&Bs[buf ^ 1][brow][bcol] = bv2;
            __syncthreads();
            buf ^= 1;
        }
    }

#pragma unroll
    for (int i = 0; i < 8; ++i) {
        int r = bm + (ty << 3) + i;
        float* Cr = C + (size_t)r * ldc + bn + (tx << 3);
#pragma unroll
        for (int j = 0; j < 8; ++j) {
            float vv = acc[i][j];
            if (bias) vv += bias[bn + (tx << 3) + j];
            if (doRelu) vv = fmaxf(vv, 0.f);
            Cr[j] = vv;
        }
    }
}

// ---------------- position packing: (x, y, z, |p|^2) ----------------
__global__ void pack_pos(const float* __restrict__ pos, float4* __restrict__ out, int n)
{
    int i = blockIdx.x * blockDim.x + threadIdx.x;
    if (i >= n) return;
    float x = pos[i * 3 + 0], y = pos[i * 3 + 1], z = pos[i * 3 + 2];
    out[i] = make_float4(x, y, z, x * x + y * y + z * z);
}

// ---------------- pack wq|wk|wv -> [L,128,384] ----------------
__global__ void pack_qkv(const float* __restrict__ wq, const float* __restrict__ wk,
                         const float* __restrict__ wv, float* __restrict__ out)
{
    int i = blockIdx.x * blockDim.x + threadIdx.x;
    if (i >= LTOT * ADIM * ADIM) return;
    int li = i / (ADIM * ADIM);
    int r = (i / ADIM) % ADIM;
    int c = i % ADIM;
    float* o = out + ((size_t)li * ADIM + r) * QKVS;
    o[c] = wq[i];
    o[ADIM + c] = wk[i];
    o[2 * ADIM + c] = wv[i];
}

// ---------------- strided copy of vox h0 into feat cols [0:128) ----------------
__global__ void copy_to_feat(const float* __restrict__ src, float* __restrict__ feat)
{
    int i = blockIdx.x * blockDim.x + threadIdx.x;
    if (i >= NV * ADIM) return;
    int r = i >> 7, c = i & 127;
    feat[(size_t)r * 640 + c] = src[i];
}

// ---------------- warp-cooperative brute-force KNN ----------------
// One warp per dst; distributed sorted top-K across lanes; ballot + whole-warp
// shuffle-up insert (no divergent insertion sort). Exact reference semantics:
// d2 = |a|^2 + |b|^2 - 2 a.b, lexicographic (d2, idx) stable tie-break.
template <int KK, bool EXCL>
__global__ __launch_bounds__(256)
void knn_warp(const float4* __restrict__ dpos4, const float4* __restrict__ spos4,
              int Ns, int* __restrict__ outIdx)
{
    const int TS = 1024;
    const unsigned FULL = 0xffffffffu;
    __shared__ float4 s4[TS];
    int lane = threadIdx.x & 31;
    int warp = threadIdx.x >> 5;
    int dst = blockIdx.x * 8 + warp;

    float4 p = dpos4[dst];

    float ld = __int_as_float(0x7f800000);  // +inf
    int   li = 0x7fffffff;
    float T  = ld;
    int   Ti = li;

    for (int t0 = 0; t0 < Ns; t0 += TS) {
        int tn = Ns - t0; if (tn > TS) tn = TS;
        __syncthreads();
        for (int i = threadIdx.x; i < tn; i += 256) s4[i] = spos4[t0 + i];
        __syncthreads();
        for (int j = lane; j < tn; j += 32) {
            int si = t0 + j;
            float4 qv = s4[j];
            float dot = fmaf(p.z, qv.z, fmaf(p.y, qv.y, p.x * qv.x));
            float d2 = (p.w + qv.w) - 2.0f * dot;
            if (EXCL && si == dst) { d2 = __int_as_float(0x7f800000); si = 0x7fffffff; }
            bool pass = (d2 < T) || (d2 == T && si < Ti);
            unsigned m = __ballot_sync(FULL, pass);
            while (m) {
                int s = __ffs(m) - 1;
                float cd = __shfl_sync(FULL, d2, s);
                int   ci = __shfl_sync(FULL, si, s);
                bool before = (cd < ld) || (cd == ld && ci < li);
                unsigned bm = __ballot_sync(FULL, before);
                float ud = __shfl_up_sync(FULL, ld, 1);
                int   ui = __shfl_up_sync(FULL, li, 1);
                int firstBefore = __ffs(bm) - 1;
                if (before) {
                    if (lane == firstBefore) { ld = cd; li = ci; }
                    else                     { ld = ud; li = ui; }
                }
                T  = __shfl_sync(FULL, ld, KK - 1);
                Ti = __shfl_sync(FULL, li, KK - 1);
                pass = pass && (lane > s) && ((d2 < T) || (d2 == T && si < Ti));
                m = __ballot_sync(FULL, pass);
            }
        }
    }
    if (lane < KK) outIdx[dst * KK + lane] = li;
}

// ---------------- per-row 128->8 projection (edge MLP first layer halves)
__global__ void proj8_kernel(const float* __restrict__ H, int Nrows,
                             const float* __restrict__ W, float* __restrict__ out)
{
    int w = (blockIdx.x * blockDim.x + threadIdx.x) >> 5;
    int lane = threadIdx.x & 31;
    if (w >= Nrows) return;
    const float* hr = H + (size_t)w * ADIM;
    float acc[8];
#pragma unroll
    for (int m = 0; m < 8; ++m) acc[m] = 0.f;
    for (int f = lane; f < ADIM; f += 32) {
        float hv = hr[f];
        const float* wr = W + f * 8;
#pragma unroll
        for (int m = 0; m < 8; ++m) acc[m] = fmaf(hv, wr[m], acc[m]);
    }
#pragma unroll
    for (int off = 16; off > 0; off >>= 1) {
#pragma unroll
        for (int m = 0; m < 8; ++m) acc[m] += __shfl_xor_sync(0xffffffffu, acc[m], off);
    }
    if (lane == 0) {
#pragma unroll
        for (int m = 0; m < 8; ++m) out[w * 8 + m] = acc[m];
    }
}

// ---------------- edge weight MLP (decomposed) + unified neighbor table write
__global__ void edgew_kernel(const int* __restrict__ nbr, int E, int Kk,
                             const float* __restrict__ dstPos, const float* __restrict__ srcPos,
                             const float* __restrict__ pSrc, const float* __restrict__ pDst,
                             const float* __restrict__ w1d, const float* __restrict__ b1,
                             const float* __restrict__ w2, const float* __restrict__ b2v,
                             int* __restrict__ Uidx, float* __restrict__ Uew,
                             int dstNodeBase, int slotOff, int srcGlobalOff)
{
    int e = blockIdx.x * blockDim.x + threadIdx.x;
    if (e >= E) return;
    int dl = e / Kk, slot = e - dl * Kk;
    int s = nbr[e];
    float dx = dstPos[dl * 3 + 0] - srcPos[s * 3 + 0];
    float dy = dstPos[dl * 3 + 1] - srcPos[s * 3 + 1];
    float dz = dstPos[dl * 3 + 2] - srcPos[s * 3 + 2];
    float ss = fmaf(dz, dz, fmaf(dy, dy, dx * dx));
    float d = sqrtf(ss + 1e-12f);
    float ew = b2v[0];
#pragma unroll
    for (int m = 0; m < 8; ++m) {
        float hmid = pSrc[s * 8 + m] + pDst[dl * 8 + m] + d * w1d[m] + b1[m];
        ew = fmaf(fmaxf(hmid, 0.f), w2[m], ew);
    }
    int un = dstNodeBase + dl;
    Uidx[un * MAXDEG + slotOff + slot] = srcGlobalOff + s;
    Uew[un * MAXDEG + slotOff + slot] = ew;
}

// ---------------- fused attention + residual + LayerNorm (+optional snapshot)
// one block (128 threads) per dst node; q|k|v packed row stride 384.
// k rows never hit smem: each float4 k-load folds into a partial q.k dot,
// reduced over 8-lane groups into logitS[deg][head]. v staged via float4.
__global__ void attn_kernel(const float* __restrict__ qkv,
                            const int* __restrict__ Uidx, const float* __restrict__ Uew,
                            float* __restrict__ h,
                            const float* __restrict__ lng, const float* __restrict__ lnb,
                            float* __restrict__ snap,   // stride 640 if non-null
                            int nodeBase)
{
    const unsigned FULL = 0xffffffffu;
    __shared__ __align__(16) float vs[MAXDEG][132];
    __shared__ __align__(16) float qs[ADIM];
    __shared__ float logitS[MAXDEG][5];
    __shared__ int   srcs[MAXDEG];
    __shared__ float ews[MAXDEG];
    __shared__ float red[8];

    int n = nodeBase + blockIdx.x;
    int t = threadIdx.x;
    int warp = t >> 5, lane = t & 31;
    int deg = (n < NA) ? KAA : MAXDEG;

    if (t < deg) { srcs[t] = Uidx[n * MAXDEG + t]; ews[t] = Uew[n * MAXDEG + t]; }
    qs[t] = qkv[(size_t)n * QKVS + t];
    __syncthreads();

    float4 q4 = ((const float4*)qs)[lane];   // cols 4*lane .. 4*lane+3 (head = lane>>3)
    for (int j = warp; j < deg; j += 4) {
        const float4* base = (const float4*)(qkv + (size_t)srcs[j] * QKVS);
        float4 k4 = base[32 + lane];     // k row floats [128,256)
        float4 v4 = base[64 + lane];     // v row floats [256,384)
        *(float4*)&vs[j][lane << 2] = v4;
        float p = fmaf(k4.w, q4.w, fmaf(k4.z, q4.z, fmaf(k4.y, q4.y, k4.x * q4.x)));
        p += __shfl_xor_sync(FULL, p, 1);
        p += __shfl_xor_sync(FULL, p, 2);
        p += __shfl_xor_sync(FULL, p, 4);
        if ((lane & 7) == 0) logitS[j][lane >> 3] = p;
    }
    __syncthreads();

    // softmax per head (warp == head), lane j handles neighbor j
    int head = warp;
    float logit = -3.0e38f;
    if (lane < deg)
        logit = logitS[lane][head] * 0.17677669529663687f + ews[lane];
    float m = logit;
#pragma unroll
    for (int off = 16; off > 0; off >>= 1)
        m = fmaxf(m, __shfl_xor_sync(FULL, m, off));
    float z = (lane < deg) ? expf(logit - m) : 0.f;
    float ssum = z;
#pragma unroll
    for (int off = 16; off > 0; off >>= 1)
        ssum += __shfl_xor_sync(FULL, ssum, off);
    float alpha = z / (ssum + 1e-9f);

    float acc = 0.f;
    for (int j = 0; j < deg; ++j) {
        float a = __shfl_sync(FULL, alpha, j);
        acc = fmaf(a, vs[j][(head << 5) + lane], acc);
    }

    // residual + LN
    float y = h[(size_t)n * ADIM + t] + acc;
    float s1 = y, s2 = y * y;
#pragma unroll
    for (int off = 16; off > 0; off >>= 1) {
        s1 += __shfl_xor_sync(FULL, s1, off);
        s2 += __shfl_xor_sync(FULL, s2, off);
    }
    if (lane == 0) { red[warp] = s1; red[4 + warp] = s2; }
    __syncthreads();
    float t1 = red[0] + red[1] + red[2] + red[3];
    float t2 = red[4] + red[5] + red[6] + red[7];
    float mu = t1 * (1.0f / ADIM);
    float var = fmaxf(t2 * (1.0f / ADIM) - mu * mu, 0.f);
    float outv = (y - mu) * rsqrtf(var + 1e-5f) * lng[t] + lnb[t];
    h[(size_t)n * ADIM + t] = outv;
    if (snap != nullptr && n >= NA) snap[(size_t)(n - NA) * 640 + t] = outv;
}

// ---------------- host ----------------
extern "C" void kernel_launch(void* const* d_in, const int* in_sizes, int n_in,
                              void* d_out, int out_size)
{
    const float* atom_x    = (const float*)d_in[0];
    const float* atom_pos  = (const float*)d_in[1];
    const float* vox_x     = (const float*)d_in[2];
    const float* vox_pos   = (const float*)d_in[3];
    const float* w_atom_in = (const float*)d_in[4];
    const float* b_atom_in = (const float*)d_in[5];
    const float* w_vox_in  = (const float*)d_in[6];
    const float* b_vox_in  = (const float*)d_in[7];
    const float* aa_w1 = (const float*)d_in[8];
    const float* aa_b1 = (const float*)d_in[9];
    const float* aa_w2 = (const float*)d_in[10];
    const float* aa_b2 = (const float*)d_in[11];
    const float* av_w1 = (const float*)d_in[12];
    const float* av_b1 = (const float*)d_in[13];
    const float* av_w2 = (const float*)d_in[14];
    const float* av_b2 = (const float*)d_in[15];
    const float* vv_w1 = (const float*)d_in[16];
    const float* vv_b1 = (const float*)d_in[17];
    const float* vv_w2 = (const float*)d_in[18];
    const float* vv_b2 = (const float*)d_in[19];
    const float* wq   = (const float*)d_in[20];
    const float* wk   = (const float*)d_in[21];
    const float* wv   = (const float*)d_in[22];
    const float* ln_g = (const float*)d_in[23];
    const float* ln_b = (const float*)d_in[24];
    const float* w_o1 = (const float*)d_in[25];
    const float* b_o1 = (const float*)d_in[26];
    const float* w_o2 = (const float*)d_in[27];
    const float* b_o2 = (const float*)d_in[28];
    float* out = (float*)d_out;
    (void)in_sizes; (void)n_in; (void)out_size;

    float *h, *qkv, *wqkv, *Uew, *paas, *paad, *pavd, *pavs, *pvvs, *pvvd, *feat, *hidden;
    float4 *apos4, *vpos4;
    int *aaIdx, *avIdx, *vvIdx, *Uidx;
    cudaGetSymbolAddress((void**)&h, g_h);
    cudaGetSymbolAddress((void**)&qkv, g_qkv);
    cudaGetSymbolAddress((void**)&wqkv, g_wqkv);
    cudaGetSymbolAddress((void**)&apos4, g_apos4);
    cudaGetSymbolAddress((void**)&vpos4, g_vpos4);
    cudaGetSymbolAddress((void**)&aaIdx, g_aa);
    cudaGetSymbolAddress((void**)&avIdx, g_av);
    cudaGetSymbolAddress((void**)&vvIdx, g_vv);
    cudaGetSymbolAddress((void**)&Uidx, g_Uidx);
    cudaGetSymbolAddress((void**)&Uew, g_Uew);
    cudaGetSymbolAddress((void**)&paas, g_paas);
    cudaGetSymbolAddress((void**)&paad, g_paad);
    cudaGetSymbolAddress((void**)&pavd, g_pavd);
    cudaGetSymbolAddress((void**)&pavs, g_pavs);
    cudaGetSymbolAddress((void**)&pvvs, g_pvvs);
    cudaGetSymbolAddress((void**)&pvvd, g_pvvd);
    cudaGetSymbolAddress((void**)&feat, g_feat);
    cudaGetSymbolAddress((void**)&hidden, g_hidden);

    const float* voxh0 = h + (size_t)NA * ADIM;   // valid until layer loop mutates h

    // one-time side stream + events (created on the non-captured correctness
    // call; during capture they only contribute fork/join edges to the graph)
    static cudaStream_t sKnn = nullptr;
    static cudaEvent_t eFork = nullptr, eProj = nullptr, eEdges = nullptr;
    if (sKnn == nullptr) {
        cudaStreamCreate(&sKnn);
        cudaEventCreateWithFlags(&eFork, cudaEventDisableTiming);
        cudaEventCreateWithFlags(&eProj, cudaEventDisableTiming);
        cudaEventCreateWithFlags(&eEdges, cudaEventDisableTiming);
    }

    // fork: KNN chain on side stream, feature chain on main stream
    cudaEventRecord(eFork, 0);
    cudaStreamWaitEvent(sKnn, eFork, 0);

    // side stream: positions + KNN graphs
    pack_pos<<<(NA + 255) / 256, 256, 0, sKnn>>>(atom_pos, apos4, NA);
    pack_pos<<<(NV + 255) / 256, 256, 0, sKnn>>>(vox_pos, vpos4, NV);
    knn_warp<KAA, true><<<NA / 8, 256, 0, sKnn>>>(apos4, apos4, NA, aaIdx);
    knn_warp<KVV, false><<<NV / 8, 256, 0, sKnn>>>(vpos4, apos4, NA, avIdx);
    knn_warp<KVV, true><<<NV / 8, 256, 0, sKnn>>>(vpos4, vpos4, NV, vvIdx);

    // main stream: weight packing, input projections, edge-MLP projections
    pack_qkv<<<(LTOT * ADIM * ADIM + 255) / 256, 256>>>(wq, wk, wv, wqkv);
    gemm128<<<dim3(NA / 128, ADIM / 128), 256>>>(atom_x, w_atom_in, b_atom_in, h, FDIM, ADIM, 0, ADIM);
    gemm128<<<dim3(NV / 128, ADIM / 128), 256>>>(vox_x, w_vox_in, b_vox_in, (float*)voxh0, FDIM, ADIM, 0, ADIM);
    copy_to_feat<<<(NV * ADIM + 255) / 256, 256>>>(voxh0, feat);
    proj8_kernel<<<NA / 8, 256>>>(h, NA, aa_w1, paas);                 // aa: i0 = src atom
    proj8_kernel<<<NA / 8, 256>>>(h, NA, aa_w1 + 128 * 8, paad);       // aa: i1 = dst atom
    proj8_kernel<<<NV / 8, 256>>>(voxh0, NV, av_w1, pavd);             // av: i0 = vox (dst)
    proj8_kernel<<<NA / 8, 256>>>(h, NA, av_w1 + 128 * 8, pavs);       // av: i1 = atom (src)
    proj8_kernel<<<NV / 8, 256>>>(voxh0, NV, vv_w1, pvvs);             // vv: i0 = src vox
    proj8_kernel<<<NV / 8, 256>>>(voxh0, NV, vv_w1 + 128 * 8, pvvd);   // vv: i1 = dst vox
    cudaEventRecord(eProj, 0);

    // side stream: edge weights (needs KNN + projections)
    cudaStreamWaitEvent(sKnn, eProj, 0);
    edgew_kernel<<<(NA * KAA + 255) / 256, 256, 0, sKnn>>>(aaIdx, NA * KAA, KAA, atom_pos, atom_pos,
        paas, paad, aa_w1 + 256 * 8, aa_b1, aa_w2, aa_b2, Uidx, Uew, 0, 0, 0);
    edgew_kernel<<<(NV * KVV + 255) / 256, 256, 0, sKnn>>>(avIdx, NV * KVV, KVV, vox_pos, atom_pos,
        pavs, pavd, av_w1 + 256 * 8, av_b1, av_w2, av_b2, Uidx, Uew, NA, 0, 0);
    edgew_kernel<<<(NV * KVV + 255) / 256, 256, 0, sKnn>>>(vvIdx, NV * KVV, KVV, vox_pos, vox_pos,
        pvvs, pvvd, vv_w1 + 256 * 8, vv_b1, vv_w2, vv_b2, Uidx, Uew, NA, KVV, NA);
    cudaEventRecord(eEdges, sKnn);

    // main stream: first QKV GEMM overlaps edge-weight computation
    gemm128<<<dim3(NN / 128, QKVS / 128), 256>>>(h, wqkv, nullptr, qkv, ADIM, QKVS, 0, QKVS);
    cudaStreamWaitEvent(0, eEdges, 0);   // join before first attention

    // attention stack (8 layers); last layer only needs vox nodes
    for (int li = 0; li < LTOT; ++li) {
        if (li > 0)
            gemm128<<<dim3(NN / 128, QKVS / 128), 256>>>(h, wqkv + (size_t)li * ADIM * QKVS,
                                                         nullptr, qkv, ADIM, QKVS, 0, QKVS);
        float* snap = (li & 1) ? (feat + (size_t)((li >> 1) + 1) * ADIM) : nullptr;
        if (li == LTOT - 1) {
            attn_kernel<<<NV, 128>>>(qkv, Uidx, Uew, h,
                                     ln_g + (size_t)li * ADIM, ln_b + (size_t)li * ADIM, snap, NA);
        } else {
            attn_kernel<<<NN, 128>>>(qkv, Uidx, Uew, h,
                                     ln_g + (size_t)li * ADIM, ln_b + (size_t)li * ADIM, snap, 0);
        }
    }

    // output head: feat [NV,640] -> relu -> [NV,128] -> [NV,128]
    gemm128<<<dim3(NV / 128, ADIM / 128), 256>>>(feat, w_o1, b_o1, hidden, 640, ADIM, 1, ADIM);
    gemm128<<<dim3(NV / 128, OUTD / 128), 256>>>(hidden, w_o2, b_o2, out, ADIM, OUTD, 0, OUTD);
}